// round 4
// baseline (speedup 1.0000x reference)
#include <cuda_runtime.h>
#include <math.h>

#define N_WL 262144
#define T_REF 273.15f
#define P_REF 101325.0f

// ---- compile-time line constants (LINES / MASS from the problem) ----
__constant__ float c_nu0[10]  = {254.0f, 280.0f, 310.0f, 940.0f, 1130.0f, 1380.0f, 1400.0f, 1600.0f, 2000.0f, 2700.0f};
__constant__ float c_str[10]  = {1.15e-17f, 5e-18f, 1.9e-19f, 2.5e-23f, 8.2e-24f, 1.8e-22f, 3.5e-25f, 7.8e-26f, 4.2e-24f, 1.2e-24f};
__constant__ float c_wid[10]  = {2.0f, 3.0f, 2.5f, 3.0f, 2.5f, 4.0f, 3.0f, 2.5f, 4.0f, 3.5f};
__constant__ float c_tex[10]  = {0.05f, 0.04f, 0.03f, 0.4f, 0.35f, 0.45f, 0.5f, 0.48f, 0.52f, 0.49f};
__constant__ float c_mass[10] = {48.0f, 48.0f, 48.0f, 18.0f, 18.0f, 18.0f, 44.0f, 44.0f, 44.0f, 44.0f};

// ---- cross-kernel scratch (allocation-free: __device__ globals) ----
__device__ float  g_h[32];     // continuum hidden
__device__ float  g_m[64];     // mixing hidden (after layer 2)
__device__ float4 g_line[10];  // {nu0, 1/(sigma+eps), y, conc*strength_T/(sigma*sqrt(pi)+eps)}

// Voigt real part w(x,y) with the reference's 3-branch select.
__device__ __forceinline__ float voigt_w(float x, float y) {
    float ax = fabsf(x);
    float s  = ax + y;
    float x2 = x * x;
    // branch 1 (s >= 15): w1 = Re(0.5641896*t / (0.5 + t^2)), t = y - i x
    float a   = 0.5f + y * y - x2;   // Re(0.5 + t^2)
    float b   = 2.0f * x * y;        // -Im(0.5 + t^2)
    float num = y * a + x * b;
    float den = a * a + b * b;
    float w   = 0.5641896f * num / den;
    if (s < 15.0f) {
        float ur = y * y - x2;       // Re(t^2)
        float ui = -2.0f * x * y;    // Im(t^2)
        if (ax >= 5.5f) {
            // w2 = Re( t*(1.410474 + 0.5641896*u) / (0.75 + u*(3+u)) )
            float cr = 1.410474f + 0.5641896f * ur;
            float ci = 0.5641896f * ui;
            float nr = y * cr + x * ci;
            float ni = y * ci - x * cr;
            float dr = 0.75f + ur * (3.0f + ur) - ui * ui;
            float di = ui * (3.0f + 2.0f * ur);
            w = (nr * dr + ni * di) / (dr * dr + di * di);
        } else {
            // w3 = exp(-x^2)cos(2xy)/sqrt(pi) + (2y/pi) sin(x^2)/(x^2+y^2+1e-10)
            w = expf(-x2) * cosf(2.0f * x * y) * 0.56418958354f
              + (2.0f * y * 0.31830988618f) * sinf(x2) / (x2 + y * y + 1e-10f);
        }
    }
    return w;
}

__device__ __forceinline__ float siluf(float z)     { return z / (1.0f + expf(-z)); }
__device__ __forceinline__ float softplusf(float z) { return fmaxf(z, 0.0f) + log1pf(expf(-fabsf(z))); }
__device__ __forceinline__ float sigmoidf(float z)  { return 1.0f / (1.0f + expf(-z)); }

// ---- kernel 1: all scalar / small-MLP work ----
__global__ void setup_kernel(
    const float* __restrict__ wl,
    const float* __restrict__ Tp, const float* __restrict__ Pp,
    const float* __restrict__ o3p, const float* __restrict__ h2op, const float* __restrict__ co2p,
    const float* __restrict__ mix_w1, const float* __restrict__ mix_b1,
    const float* __restrict__ mix_w2, const float* __restrict__ mix_b2,
    const float* __restrict__ cont_w1, const float* __restrict__ cont_b1,
    const float* __restrict__ cont_w2, const float* __restrict__ cont_b2)
{
    __shared__ float  s_h[32];
    __shared__ float  s_cross8[8];
    __shared__ float  s_mf[10];
    __shared__ float  s_a1[64];
    __shared__ float4 s_line[10];

    const int t = threadIdx.x;
    const float T = *Tp, P = *Pp;
    const float cO3 = *o3p, cH2O = *h2op, cCO2 = *co2p;

    // continuum hidden: h = silu(feat @ cont_w1 + cont_b1)
    if (t < 32) {
        float feat[5] = { T / (T_REF + 1e-12f), P / (P_REF + 1e-12f), cH2O, 1.0f, 0.0f };
        float z = cont_b1[t];
        #pragma unroll
        for (int i = 0; i < 5; i++) z += feat[i] * cont_w1[i * 32 + t];
        float hv = siluf(z);
        s_h[t] = hv;
        g_h[t] = hv;
    }
    // line parameters
    if (t < 10) {
        float nu0  = c_nu0[t];
        float conc = (t < 3) ? cO3 : ((t < 6) ? cH2O : cCO2);
        float sT   = c_str[t] * powf(T_REF / (T + 1e-12f), c_tex[t]);
        float gL   = c_wid[t] * (P / (P_REF + 1e-12f)) * sqrtf(T_REF / (T + 1e-12f));
        float gD   = nu0 / 299792458.0f * sqrtf(2.0f * 1.380649e-23f * T * 6.02214076e23f / (c_mass[t] + 1e-12f));
        float sigma = gD / (1.1774100226f + 1e-12f);   // sqrt(2*ln2)
        float y    = gL / (sigma + 1e-12f);
        float4 L;
        L.x = nu0;
        L.y = 1.0f / (sigma + 1e-12f);
        L.z = y;
        L.w = conc * sT / (sigma * 1.77245385091f + 1e-12f);  // amp / (sigma*sqrt(pi)+eps)
        s_line[t] = L;
        g_line[t] = L;
    }
    __syncthreads();

    // cross[0..7] = voigt sum + continuum at first 8 wavelengths
    if (t < 8) {
        float wlv = wl[t];
        float cr = 0.0f;
        #pragma unroll
        for (int l = 0; l < 10; l++) {
            float4 L = s_line[l];
            cr += L.w * voigt_w((wlv - L.x) * L.y, L.z);
        }
        float z = cont_b2[t];
        #pragma unroll
        for (int k = 0; k < 32; k++) z += s_h[k] * cont_w2[k * N_WL + t];
        cr += softplusf(z);
        s_cross8[t] = cr;
    }
    __syncthreads();

    if (t == 0) { s_mf[0] = T / (T_REF + 1e-12f); s_mf[1] = P / (P_REF + 1e-12f); }
    if (t < 8)  { s_mf[2 + t] = s_cross8[t]; }
    __syncthreads();

    // mixing MLP layer 1: 10 -> 64
    if (t < 64) {
        float z = mix_b1[t];
        #pragma unroll
        for (int i = 0; i < 10; i++) z += s_mf[i] * mix_w1[i * 64 + t];
        s_a1[t] = siluf(z);
    }
    __syncthreads();
    // layer 2: 64 -> 64
    if (t < 64) {
        float z = mix_b2[t];
        #pragma unroll
        for (int i = 0; i < 64; i++) z += s_a1[i] * mix_w2[i * 64 + t];
        g_m[t] = siluf(z);
    }
}

// ---- kernel 2: fused streaming pass over all wavelengths (float4 per thread) ----
__global__ void __launch_bounds__(128) main_kernel(
    const float* __restrict__ wl,
    const float* __restrict__ mix_w3, const float* __restrict__ mix_b3,
    const float* __restrict__ cont_w2, const float* __restrict__ cont_b2,
    float* __restrict__ out)
{
    __shared__ float  sh[32];
    __shared__ float  sm[64];
    __shared__ float4 sl[10];

    const int t = threadIdx.x;
    if (t < 32) sh[t] = g_h[t];
    if (t < 64) sm[t] = g_m[t];
    if (t < 10) sl[t] = g_line[t];
    __syncthreads();

    const int j4 = blockIdx.x * blockDim.x + t;   // index in float4 units
    const float4* __restrict__ wl4 = (const float4*)wl;
    const float4* __restrict__ cw2 = (const float4*)cont_w2;
    const float4* __restrict__ mw3 = (const float4*)mix_w3;

    float4 w = wl4[j4];

    // Voigt line sum
    float v0 = 0.f, v1 = 0.f, v2 = 0.f, v3 = 0.f;
    #pragma unroll
    for (int l = 0; l < 10; l++) {
        float4 L = sl[l];
        v0 += L.w * voigt_w((w.x - L.x) * L.y, L.z);
        v1 += L.w * voigt_w((w.y - L.x) * L.y, L.z);
        v2 += L.w * voigt_w((w.z - L.x) * L.y, L.z);
        v3 += L.w * voigt_w((w.w - L.x) * L.y, L.z);
    }

    // continuum: softplus(h . cont_w2[:,j] + b2)
    float4 c = ((const float4*)cont_b2)[j4];
    #pragma unroll 8
    for (int k = 0; k < 32; k++) {
        float4 wv = cw2[k * (N_WL / 4) + j4];
        float hk = sh[k];
        c.x += hk * wv.x; c.y += hk * wv.y; c.z += hk * wv.z; c.w += hk * wv.w;
    }
    float cr0 = v0 + softplusf(c.x);
    float cr1 = v1 + softplusf(c.y);
    float cr2 = v2 + softplusf(c.z);
    float cr3 = v3 + softplusf(c.w);

    // mixing: sigmoid(m . mix_w3[:,j] + b3)
    float4 z = ((const float4*)mix_b3)[j4];
    #pragma unroll 8
    for (int k = 0; k < 64; k++) {
        float4 wv = mw3[k * (N_WL / 4) + j4];
        float mk = sm[k];
        z.x += mk * wv.x; z.y += mk * wv.y; z.z += mk * wv.z; z.w += mk * wv.w;
    }

    float4 o;
    o.x = cr0 * (1.0f + 0.1f * (sigmoidf(z.x) - 0.5f));
    o.y = cr1 * (1.0f + 0.1f * (sigmoidf(z.y) - 0.5f));
    o.z = cr2 * (1.0f + 0.1f * (sigmoidf(z.z) - 0.5f));
    o.w = cr3 * (1.0f + 0.1f * (sigmoidf(z.w) - 0.5f));
    ((float4*)out)[j4] = o;
}

extern "C" void kernel_launch(void* const* d_in, const int* in_sizes, int n_in,
                              void* d_out, int out_size)
{
    const float* wl      = (const float*)d_in[0];
    const float* Tp      = (const float*)d_in[1];
    const float* Pp      = (const float*)d_in[2];
    const float* o3      = (const float*)d_in[3];
    const float* h2o     = (const float*)d_in[4];
    const float* co2     = (const float*)d_in[5];
    const float* mix_w1  = (const float*)d_in[6];
    const float* mix_b1  = (const float*)d_in[7];
    const float* mix_w2  = (const float*)d_in[8];
    const float* mix_b2  = (const float*)d_in[9];
    const float* mix_w3  = (const float*)d_in[10];
    const float* mix_b3  = (const float*)d_in[11];
    const float* cont_w1 = (const float*)d_in[12];
    const float* cont_b1 = (const float*)d_in[13];
    const float* cont_w2 = (const float*)d_in[14];
    const float* cont_b2 = (const float*)d_in[15];
    float* out = (float*)d_out;

    setup_kernel<<<1, 64>>>(wl, Tp, Pp, o3, h2o, co2,
                            mix_w1, mix_b1, mix_w2, mix_b2,
                            cont_w1, cont_b1, cont_w2, cont_b2);

    const int threads = 128;
    const int blocks  = (N_WL / 4) / threads;  // 512 blocks
    main_kernel<<<blocks, threads>>>(wl, mix_w3, mix_b3, cont_w2, cont_b2, out);
}

// round 5
// speedup vs baseline: 1.6330x; 1.6330x over previous
#include <cuda_runtime.h>
#include <math.h>

#define N_WL 262144
#define T_REF 273.15f
#define P_REF 101325.0f

// ---- compile-time line constants (LINES / MASS from the problem) ----
__constant__ float c_nu0[10]  = {254.0f, 280.0f, 310.0f, 940.0f, 1130.0f, 1380.0f, 1400.0f, 1600.0f, 2000.0f, 2700.0f};
__constant__ float c_str[10]  = {1.15e-17f, 5e-18f, 1.9e-19f, 2.5e-23f, 8.2e-24f, 1.8e-22f, 3.5e-25f, 7.8e-26f, 4.2e-24f, 1.2e-24f};
__constant__ float c_wid[10]  = {2.0f, 3.0f, 2.5f, 3.0f, 2.5f, 4.0f, 3.0f, 2.5f, 4.0f, 3.5f};
__constant__ float c_tex[10]  = {0.05f, 0.04f, 0.03f, 0.4f, 0.35f, 0.45f, 0.5f, 0.48f, 0.52f, 0.49f};
__constant__ float c_mass[10] = {48.0f, 48.0f, 48.0f, 18.0f, 18.0f, 18.0f, 44.0f, 44.0f, 44.0f, 44.0f};

// ---- cross-kernel scratch (allocation-free: __device__ globals) ----
__device__ float  g_h[32];     // continuum hidden
__device__ float  g_m[64];     // mixing hidden (after layer 2)
__device__ float4 g_line[10];  // {nu0, 1/(sigma+eps), y, conc*strength_T/(sigma*sqrt(pi)+eps)}

// Voigt real part w(x,y) with the reference's 3-branch select.
__device__ __forceinline__ float voigt_w(float x, float y) {
    float ax = fabsf(x);
    float s  = ax + y;
    float x2 = x * x;
    // branch 1 (s >= 15): w1 = Re(0.5641896*t / (0.5 + t^2)), t = y - i x
    float a   = 0.5f + y * y - x2;   // Re(0.5 + t^2)
    float b   = 2.0f * x * y;        // -Im(0.5 + t^2)
    float num = y * a + x * b;
    float den = a * a + b * b;
    float w   = 0.5641896f * num / den;
    if (s < 15.0f) {
        float ur = y * y - x2;       // Re(t^2)
        float ui = -2.0f * x * y;    // Im(t^2)
        if (ax >= 5.5f) {
            // w2 = Re( t*(1.410474 + 0.5641896*u) / (0.75 + u*(3+u)) )
            float cr = 1.410474f + 0.5641896f * ur;
            float ci = 0.5641896f * ui;
            float nr = y * cr + x * ci;
            float ni = y * ci - x * cr;
            float dr = 0.75f + ur * (3.0f + ur) - ui * ui;
            float di = ui * (3.0f + 2.0f * ur);
            w = (nr * dr + ni * di) / (dr * dr + di * di);
        } else {
            // w3 = exp(-x^2)cos(2xy)/sqrt(pi) + (2y/pi) sin(x^2)/(x^2+y^2+1e-10)
            w = expf(-x2) * cosf(2.0f * x * y) * 0.56418958354f
              + (2.0f * y * 0.31830988618f) * sinf(x2) / (x2 + y * y + 1e-10f);
        }
    }
    return w;
}

__device__ __forceinline__ float siluf(float z)     { return z / (1.0f + expf(-z)); }
__device__ __forceinline__ float softplusf(float z) { return fmaxf(z, 0.0f) + log1pf(expf(-fabsf(z))); }
__device__ __forceinline__ float sigmoidf(float z)  { return 1.0f / (1.0f + expf(-z)); }

// ---- kernel 1: all scalar / small-MLP work ----
__global__ void setup_kernel(
    const float* __restrict__ wl,
    const float* __restrict__ Tp, const float* __restrict__ Pp,
    const float* __restrict__ o3p, const float* __restrict__ h2op, const float* __restrict__ co2p,
    const float* __restrict__ mix_w1, const float* __restrict__ mix_b1,
    const float* __restrict__ mix_w2, const float* __restrict__ mix_b2,
    const float* __restrict__ cont_w1, const float* __restrict__ cont_b1,
    const float* __restrict__ cont_w2, const float* __restrict__ cont_b2)
{
    __shared__ float  s_h[32];
    __shared__ float  s_cross8[8];
    __shared__ float  s_mf[10];
    __shared__ float  s_a1[64];
    __shared__ float4 s_line[10];

    const int t = threadIdx.x;
    const float T = *Tp, P = *Pp;
    const float cO3 = *o3p, cH2O = *h2op, cCO2 = *co2p;

    // continuum hidden: h = silu(feat @ cont_w1 + cont_b1)
    if (t < 32) {
        float feat[5] = { T / (T_REF + 1e-12f), P / (P_REF + 1e-12f), cH2O, 1.0f, 0.0f };
        float z = cont_b1[t];
        #pragma unroll
        for (int i = 0; i < 5; i++) z += feat[i] * cont_w1[i * 32 + t];
        float hv = siluf(z);
        s_h[t] = hv;
        g_h[t] = hv;
    }
    // line parameters
    if (t < 10) {
        float nu0  = c_nu0[t];
        float conc = (t < 3) ? cO3 : ((t < 6) ? cH2O : cCO2);
        float sT   = c_str[t] * powf(T_REF / (T + 1e-12f), c_tex[t]);
        float gL   = c_wid[t] * (P / (P_REF + 1e-12f)) * sqrtf(T_REF / (T + 1e-12f));
        float gD   = nu0 / 299792458.0f * sqrtf(2.0f * 1.380649e-23f * T * 6.02214076e23f / (c_mass[t] + 1e-12f));
        float sigma = gD / (1.1774100226f + 1e-12f);   // sqrt(2*ln2)
        float y    = gL / (sigma + 1e-12f);
        float4 L;
        L.x = nu0;
        L.y = 1.0f / (sigma + 1e-12f);
        L.z = y;
        L.w = conc * sT / (sigma * 1.77245385091f + 1e-12f);  // amp / (sigma*sqrt(pi)+eps)
        s_line[t] = L;
        g_line[t] = L;
    }
    __syncthreads();

    // cross[0..7] = voigt sum + continuum at first 8 wavelengths
    if (t < 8) {
        float wlv = wl[t];
        float cr = 0.0f;
        #pragma unroll
        for (int l = 0; l < 10; l++) {
            float4 L = s_line[l];
            cr += L.w * voigt_w((wlv - L.x) * L.y, L.z);
        }
        float z = cont_b2[t];
        #pragma unroll
        for (int k = 0; k < 32; k++) z += s_h[k] * cont_w2[k * N_WL + t];
        cr += softplusf(z);
        s_cross8[t] = cr;
    }
    __syncthreads();

    if (t == 0) { s_mf[0] = T / (T_REF + 1e-12f); s_mf[1] = P / (P_REF + 1e-12f); }
    if (t < 8)  { s_mf[2 + t] = s_cross8[t]; }
    __syncthreads();

    // mixing MLP layer 1: 10 -> 64
    if (t < 64) {
        float z = mix_b1[t];
        #pragma unroll
        for (int i = 0; i < 10; i++) z += s_mf[i] * mix_w1[i * 64 + t];
        s_a1[t] = siluf(z);
    }
    __syncthreads();
    // layer 2: 64 -> 64
    if (t < 64) {
        float z = mix_b2[t];
        #pragma unroll
        for (int i = 0; i < 64; i++) z += s_a1[i] * mix_w2[i * 64 + t];
        g_m[t] = siluf(z);
    }
}

// ---- kernel 2: fused streaming pass, ONE wavelength per thread ----
// 262144 threads total (4x the previous float4 version) -> ~75% occupancy,
// 4x chip-wide memory-level parallelism. All loads remain fully coalesced
// (32 lanes x 4B = one 128B line per LDG).
__global__ void __launch_bounds__(256) main_kernel(
    const float* __restrict__ wl,
    const float* __restrict__ mix_w3, const float* __restrict__ mix_b3,
    const float* __restrict__ cont_w2, const float* __restrict__ cont_b2,
    float* __restrict__ out)
{
    __shared__ float  sh[32];
    __shared__ float  sm[64];
    __shared__ float4 sl[10];

    const int t = threadIdx.x;
    if (t < 32) sh[t] = g_h[t];
    if (t < 64) sm[t] = g_m[t];
    if (t < 10) sl[t] = g_line[t];
    __syncthreads();

    const int j = blockIdx.x * blockDim.x + t;

    const float wv = wl[j];

    // Voigt line sum (tiny vs continuum; always-taken branch-1 path in practice)
    float v = 0.0f;
    #pragma unroll
    for (int l = 0; l < 10; l++) {
        float4 L = sl[l];
        v += L.w * voigt_w((wv - L.x) * L.y, L.z);
    }

    // continuum: softplus(h . cont_w2[:,j] + b2)  -- 32 independent streaming loads
    float c = cont_b2[j];
    const float* __restrict__ pc = cont_w2 + j;
    #pragma unroll 16
    for (int k = 0; k < 32; k++) {
        c += sh[k] * pc[k * N_WL];
    }
    float cross = v + softplusf(c);

    // mixing: sigmoid(m . mix_w3[:,j] + b3)  -- 64 independent streaming loads
    float z = mix_b3[j];
    const float* __restrict__ pm = mix_w3 + j;
    #pragma unroll 16
    for (int k = 0; k < 64; k++) {
        z += sm[k] * pm[k * N_WL];
    }

    out[j] = cross * (1.0f + 0.1f * (sigmoidf(z) - 0.5f));
}

extern "C" void kernel_launch(void* const* d_in, const int* in_sizes, int n_in,
                              void* d_out, int out_size)
{
    const float* wl      = (const float*)d_in[0];
    const float* Tp      = (const float*)d_in[1];
    const float* Pp      = (const float*)d_in[2];
    const float* o3      = (const float*)d_in[3];
    const float* h2o     = (const float*)d_in[4];
    const float* co2     = (const float*)d_in[5];
    const float* mix_w1  = (const float*)d_in[6];
    const float* mix_b1  = (const float*)d_in[7];
    const float* mix_w2  = (const float*)d_in[8];
    const float* mix_b2  = (const float*)d_in[9];
    const float* mix_w3  = (const float*)d_in[10];
    const float* mix_b3  = (const float*)d_in[11];
    const float* cont_w1 = (const float*)d_in[12];
    const float* cont_b1 = (const float*)d_in[13];
    const float* cont_w2 = (const float*)d_in[14];
    const float* cont_b2 = (const float*)d_in[15];
    float* out = (float*)d_out;

    setup_kernel<<<1, 64>>>(wl, Tp, Pp, o3, h2o, co2,
                            mix_w1, mix_b1, mix_w2, mix_b2,
                            cont_w1, cont_b1, cont_w2, cont_b2);

    const int threads = 256;
    const int blocks  = N_WL / threads;  // 1024 blocks, 1 wavelength per thread
    main_kernel<<<blocks, threads>>>(wl, mix_w3, mix_b3, cont_w2, cont_b2, out);
}